// round 2
// baseline (speedup 1.0000x reference)
#include <cuda_runtime.h>
#include <math.h>

#define BB   128
#define NN   1024
#define DIN  192
#define HH   128
#define KK   3
#define BN   (BB*NN)
#define SCALE 0.08838834764831845f   // 1/sqrt(128)
#define LNEPS 1e-5f

// ------------------------- device scratch (no allocs allowed) ----------------
__device__ float g_inputs[(size_t)BN * HH];     // 64 MB: LN(X@Wp^T+bp)
__device__ float g_WpT[DIN * HH];
__device__ float g_WqT[HH * HH];
__device__ float g_WvT[HH * HH];
__device__ float g_WihT[HH * 3 * HH];
__device__ float g_WhhT[HH * 3 * HH];
__device__ float g_W1T[HH * 2 * HH];
__device__ float g_W2T[2 * HH * HH];
__device__ float g_slots[BB * KK * HH];
__device__ float g_qk[BB * KK * HH];
__device__ float g_qc[BB * KK];
__device__ float g_upd[BB * KK * HH];
__device__ float g_sumw[BB * KK];

__device__ __forceinline__ float wred(float v) {
    #pragma unroll
    for (int o = 16; o; o >>= 1) v += __shfl_xor_sync(0xFFFFFFFFu, v, o);
    return v;
}
__device__ __forceinline__ float sigmoidf_(float x) { return 1.0f / (1.0f + expf(-x)); }
__device__ __forceinline__ float gelu_exact(float x) {
    return 0.5f * x * (1.0f + erff(x * 0.7071067811865476f));
}

// ------------------------- weight transposes (one-time-ish, cheap) ----------
__global__ void prep_transpose(const float* __restrict__ Wp, const float* __restrict__ Wq,
                               const float* __restrict__ Wv, const float* __restrict__ Wih,
                               const float* __restrict__ Whh, const float* __restrict__ W1,
                               const float* __restrict__ W2) {
    int i = blockIdx.x * blockDim.x + threadIdx.x;
    int stride = gridDim.x * blockDim.x;
    // Wp (128,192) -> WpT[e*128+j]
    for (int t = i; t < HH * DIN; t += stride) { int j = t / DIN, e = t % DIN; g_WpT[e * HH + j] = Wp[t]; }
    // Wq (128,128) -> WqT[e*128+j]
    for (int t = i; t < HH * HH; t += stride) { int j = t / HH, e = t % HH; g_WqT[e * HH + j] = Wq[t]; }
    // Wv (128,128) -> WvT[e*128+d]
    for (int t = i; t < HH * HH; t += stride) { int d = t / HH, e = t % HH; g_WvT[e * HH + d] = Wv[t]; }
    // Wih (384,128) -> WihT[d*384+o]
    for (int t = i; t < 3 * HH * HH; t += stride) { int o = t / HH, d = t % HH; g_WihT[d * (3 * HH) + o] = Wih[t]; }
    for (int t = i; t < 3 * HH * HH; t += stride) { int o = t / HH, d = t % HH; g_WhhT[d * (3 * HH) + o] = Whh[t]; }
    // W1 (256,128) -> W1T[d*256+p]
    for (int t = i; t < 2 * HH * HH; t += stride) { int p = t / HH, d = t % HH; g_W1T[d * (2 * HH) + p] = W1[t]; }
    // W2 (128,256) -> W2T[p*128+j]
    for (int t = i; t < 2 * HH * HH; t += stride) { int j = t / (2 * HH), p = t % (2 * HH); g_W2T[p * HH + j] = W2[t]; }
}

// ------------------------- slots init ----------------------------------------
__global__ void init_slots(const float* __restrict__ noise, const float* __restrict__ mu,
                           const float* __restrict__ logsig) {
    int i = blockIdx.x * blockDim.x + threadIdx.x;    // < B*K*H
    int r = i % (KK * HH);
    g_slots[i] = mu[r] + expf(logsig[r]) * noise[i];
}

// ------------------------- fused projection + LayerNorm ----------------------
// inputs = LN(X @ Wp^T + bp) ; tile 32 rows x 128 cols, K chunks of 16.
#define TM 32
#define KB 16
__global__ __launch_bounds__(256) void proj_ln_kernel(const float* __restrict__ X,
                                                      const float* __restrict__ bp,
                                                      const float* __restrict__ gin,
                                                      const float* __restrict__ bin) {
    __shared__ float xs[TM][KB];
    __shared__ float ws[KB][HH];
    const int row0 = blockIdx.x * TM;
    const int tid = threadIdx.x;
    const int tr = tid >> 5;     // 0..7  : row group (warp id)
    const int tc = tid & 31;     // 0..31 : col group (lane)

    float acc[4][4];
    #pragma unroll
    for (int i = 0; i < 4; i++)
        #pragma unroll
        for (int j = 0; j < 4; j++) acc[i][j] = 0.0f;

    for (int k0 = 0; k0 < DIN; k0 += KB) {
        #pragma unroll
        for (int l = 0; l < 2; l++) {
            int lin = l * 256 + tid;
            int r = lin >> 4, c = lin & 15;
            xs[r][c] = X[(row0 + r) * DIN + k0 + c];
        }
        #pragma unroll
        for (int l = 0; l < 8; l++) {
            int lin = l * 256 + tid;
            int kk = lin >> 7, j = lin & 127;
            ws[kk][j] = g_WpT[(k0 + kk) * HH + j];
        }
        __syncthreads();
        #pragma unroll
        for (int kk = 0; kk < KB; kk++) {
            float4 bv = *(const float4*)(&ws[kk][tc * 4]);
            float a0 = xs[tr * 4 + 0][kk];
            float a1 = xs[tr * 4 + 1][kk];
            float a2 = xs[tr * 4 + 2][kk];
            float a3 = xs[tr * 4 + 3][kk];
            acc[0][0] += a0 * bv.x; acc[0][1] += a0 * bv.y; acc[0][2] += a0 * bv.z; acc[0][3] += a0 * bv.w;
            acc[1][0] += a1 * bv.x; acc[1][1] += a1 * bv.y; acc[1][2] += a1 * bv.z; acc[1][3] += a1 * bv.w;
            acc[2][0] += a2 * bv.x; acc[2][1] += a2 * bv.y; acc[2][2] += a2 * bv.z; acc[2][3] += a2 * bv.w;
            acc[3][0] += a3 * bv.x; acc[3][1] += a3 * bv.y; acc[3][2] += a3 * bv.z; acc[3][3] += a3 * bv.w;
        }
        __syncthreads();
    }

    const float4 bias = *(const float4*)(&bp[tc * 4]);
    const float4 g4   = *(const float4*)(&gin[tc * 4]);
    const float4 b4   = *(const float4*)(&bin[tc * 4]);

    #pragma unroll
    for (int i = 0; i < 4; i++) {
        acc[i][0] += bias.x; acc[i][1] += bias.y; acc[i][2] += bias.z; acc[i][3] += bias.w;
        float s  = acc[i][0] + acc[i][1] + acc[i][2] + acc[i][3];
        float s2 = acc[i][0] * acc[i][0] + acc[i][1] * acc[i][1]
                 + acc[i][2] * acc[i][2] + acc[i][3] * acc[i][3];
        s  = wred(s);
        s2 = wred(s2);
        float mu = s * (1.0f / HH);
        float var = s2 * (1.0f / HH) - mu * mu;
        float rstd = rsqrtf(var + LNEPS);
        int row = row0 + tr * 4 + i;
        float4 o;
        o.x = (acc[i][0] - mu) * rstd * g4.x + b4.x;
        o.y = (acc[i][1] - mu) * rstd * g4.y + b4.y;
        o.z = (acc[i][2] - mu) * rstd * g4.z + b4.z;
        o.w = (acc[i][3] - mu) * rstd * g4.w + b4.w;
        *(float4*)(&g_inputs[(size_t)row * HH + tc * 4]) = o;
    }
}

// ------------------------- per-iteration: LN(slots), q, qk, c ----------------
// grid = B, 384 threads: thread = (kappa = tid>>7, j = tid&127)
__global__ __launch_bounds__(384) void ln_q_kernel(const float* __restrict__ gs,
                                                   const float* __restrict__ bs,
                                                   const float* __restrict__ bq,
                                                   const float* __restrict__ Wk,
                                                   const float* __restrict__ bk) {
    const int b = blockIdx.x;
    const int tid = threadIdx.x;
    const int ka = tid >> 7;
    const int j = tid & 127;
    __shared__ float s_s[KK][HH];
    __shared__ float q_s[KK][HH];
    __shared__ float r1[KK][4], r2[KK][4];

    float v = g_slots[(b * KK + ka) * HH + j];
    float a = wred(v), a2 = wred(v * v);
    if ((j & 31) == 0) { r1[ka][j >> 5] = a; r2[ka][j >> 5] = a2; }
    __syncthreads();
    float mu = (r1[ka][0] + r1[ka][1] + r1[ka][2] + r1[ka][3]) * (1.0f / HH);
    float var = (r2[ka][0] + r2[ka][1] + r2[ka][2] + r2[ka][3]) * (1.0f / HH) - mu * mu;
    float rstd = rsqrtf(var + LNEPS);
    s_s[ka][j] = (v - mu) * rstd * gs[j] + bs[j];
    __syncthreads();

    // q[ka][j] = bq[j] + sum_e s[ka][e] * Wq[j,e]   (WqT[e*128+j] coalesced)
    float q = bq[j];
    #pragma unroll 8
    for (int e = 0; e < HH; e++) q += s_s[ka][e] * g_WqT[e * HH + j];
    q_s[ka][j] = q;
    __syncthreads();

    // qk[ka][e=j] = SCALE * sum_d q[ka][d] * Wk[d,e] ; Wk row-major -> coalesced over e
    float qk = 0.0f;
    #pragma unroll 8
    for (int d = 0; d < HH; d++) qk += q_s[ka][d] * Wk[d * HH + j];
    g_qk[(b * KK + ka) * HH + j] = qk * SCALE;

    // c[ka] = SCALE * q . bk
    float p = wred(q_s[ka][j] * bk[j]);
    __syncthreads();
    if ((j & 31) == 0) r1[ka][j >> 5] = p;
    __syncthreads();
    if (j == 0)
        g_qc[b * KK + ka] = (r1[ka][0] + r1[ka][1] + r1[ka][2] + r1[ka][3]) * SCALE;
}

// ------------------------- per-iteration: attention stream -------------------
// grid = B, 256 threads (8 warps), each warp strides over 128 tokens.
__global__ __launch_bounds__(256) void attn_stream_kernel(float* __restrict__ attn_out) {
    const int b = blockIdx.x;
    const int tid = threadIdx.x;
    const int w = tid >> 5, lane = tid & 31;
    __shared__ float qk_s[KK][HH];
    __shared__ float wacc[8][KK][HH];
    __shared__ float wsum_s[8][KK];
    __shared__ float c_s[KK];

    for (int i = tid; i < KK * HH; i += 256) qk_s[i / HH][i % HH] = g_qk[b * KK * HH + i];
    if (tid < KK) c_s[tid] = g_qc[b * KK + tid];
    __syncthreads();

    float4 qv0 = *(const float4*)(&qk_s[0][lane * 4]);
    float4 qv1 = *(const float4*)(&qk_s[1][lane * 4]);
    float4 qv2 = *(const float4*)(&qk_s[2][lane * 4]);
    const float c0 = c_s[0], c1 = c_s[1], c2 = c_s[2];

    float f0x = 0, f0y = 0, f0z = 0, f0w = 0;
    float f1x = 0, f1y = 0, f1z = 0, f1w = 0;
    float f2x = 0, f2y = 0, f2z = 0, f2w = 0;
    float ws0 = 0, ws1 = 0, ws2 = 0;

    const float4* inp = (const float4*)(g_inputs + (size_t)b * NN * HH);
    for (int n = w; n < NN; n += 8) {
        float4 x = inp[n * 32 + lane];
        float d0 = x.x * qv0.x + x.y * qv0.y + x.z * qv0.z + x.w * qv0.w;
        float d1 = x.x * qv1.x + x.y * qv1.y + x.z * qv1.z + x.w * qv1.w;
        float d2 = x.x * qv2.x + x.y * qv2.y + x.z * qv2.z + x.w * qv2.w;
        #pragma unroll
        for (int o = 16; o; o >>= 1) {
            d0 += __shfl_xor_sync(0xFFFFFFFFu, d0, o);
            d1 += __shfl_xor_sync(0xFFFFFFFFu, d1, o);
            d2 += __shfl_xor_sync(0xFFFFFFFFu, d2, o);
        }
        d0 += c0; d1 += c1; d2 += c2;
        float m = fmaxf(d0, fmaxf(d1, d2));
        float e0 = expf(d0 - m), e1 = expf(d1 - m), e2 = expf(d2 - m);
        float inv = 1.0f / (e0 + e1 + e2);
        float a0 = e0 * inv, a1 = e1 * inv, a2 = e2 * inv;
        if (lane == 0) {
            attn_out[(b * KK + 0) * NN + n] = a0;
            attn_out[(b * KK + 1) * NN + n] = a1;
            attn_out[(b * KK + 2) * NN + n] = a2;
        }
        f0x += a0 * x.x; f0y += a0 * x.y; f0z += a0 * x.z; f0w += a0 * x.w;
        f1x += a1 * x.x; f1y += a1 * x.y; f1z += a1 * x.z; f1w += a1 * x.w;
        f2x += a2 * x.x; f2y += a2 * x.y; f2z += a2 * x.z; f2w += a2 * x.w;
        ws0 += a0; ws1 += a1; ws2 += a2;
    }
    *(float4*)(&wacc[w][0][lane * 4]) = make_float4(f0x, f0y, f0z, f0w);
    *(float4*)(&wacc[w][1][lane * 4]) = make_float4(f1x, f1y, f1z, f1w);
    *(float4*)(&wacc[w][2][lane * 4]) = make_float4(f2x, f2y, f2z, f2w);
    if (lane == 0) { wsum_s[w][0] = ws0; wsum_s[w][1] = ws1; wsum_s[w][2] = ws2; }
    __syncthreads();

    for (int i = tid; i < KK * HH; i += 256) {
        int ka = i / HH, e = i % HH;
        float s = 0;
        #pragma unroll
        for (int ww = 0; ww < 8; ww++) s += wacc[ww][ka][e];
        g_upd[b * KK * HH + i] = s;
    }
    if (tid < KK) {
        float s = 0;
        #pragma unroll
        for (int ww = 0; ww < 8; ww++) s += wsum_s[ww][tid];
        g_sumw[b * KK + tid] = s;
    }
}

// ------------------------- per-iteration: updates -> GRU -> MLP --------------
// grid = B, 384 threads: thread = (kappa, j)
__global__ __launch_bounds__(384) void post_kernel(const float* __restrict__ bv,
                                                   const float* __restrict__ bih,
                                                   const float* __restrict__ bhh,
                                                   const float* __restrict__ gm,
                                                   const float* __restrict__ bm,
                                                   const float* __restrict__ b1,
                                                   const float* __restrict__ b2,
                                                   float* __restrict__ out_slots) {
    const int b = blockIdx.x;
    const int tid = threadIdx.x;
    const int ka = tid >> 7;
    const int j = tid & 127;
    __shared__ float raw_s[KK][HH];
    __shared__ float h_s[KK][HH];
    __shared__ float x_s[KK][HH];
    __shared__ float m_s[KK][HH];
    __shared__ float t_s[KK][2 * HH];
    __shared__ float sw_s[KK];
    __shared__ float r1[KK][4], r2[KK][4];

    raw_s[ka][j] = g_upd[(b * KK + ka) * HH + j];
    h_s[ka][j]   = g_slots[(b * KK + ka) * HH + j];
    if (tid < KK) sw_s[tid] = g_sumw[b * KK + tid];
    __syncthreads();

    // updates x = raw @ Wv^T + sumw*bv
    float xv = sw_s[ka] * bv[j];
    #pragma unroll 8
    for (int e = 0; e < HH; e++) xv += raw_s[ka][e] * g_WvT[e * HH + j];
    x_s[ka][j] = xv;
    __syncthreads();

    // GRU gates
    float ai0 = bih[j], ai1 = bih[j + 128], ai2 = bih[j + 256];
    float ah0 = bhh[j], ah1 = bhh[j + 128], ah2 = bhh[j + 256];
    #pragma unroll 4
    for (int d = 0; d < HH; d++) {
        float xd = x_s[ka][d], hd = h_s[ka][d];
        ai0 += xd * g_WihT[d * 384 + j];
        ai1 += xd * g_WihT[d * 384 + j + 128];
        ai2 += xd * g_WihT[d * 384 + j + 256];
        ah0 += hd * g_WhhT[d * 384 + j];
        ah1 += hd * g_WhhT[d * 384 + j + 128];
        ah2 += hd * g_WhhT[d * 384 + j + 256];
    }
    float r = sigmoidf_(ai0 + ah0);
    float z = sigmoidf_(ai1 + ah1);
    float nn = tanhf(ai2 + r * ah2);
    float hnew = (1.0f - z) * nn + z * h_s[ka][j];

    // LN(hnew) with g_m, b_m
    float a = wred(hnew), a2 = wred(hnew * hnew);
    if ((j & 31) == 0) { r1[ka][j >> 5] = a; r2[ka][j >> 5] = a2; }
    __syncthreads();
    float mu = (r1[ka][0] + r1[ka][1] + r1[ka][2] + r1[ka][3]) * (1.0f / HH);
    float var = (r2[ka][0] + r2[ka][1] + r2[ka][2] + r2[ka][3]) * (1.0f / HH) - mu * mu;
    float rstd = rsqrtf(var + LNEPS);
    m_s[ka][j] = (hnew - mu) * rstd * gm[j] + bm[j];
    __syncthreads();

    // MLP expand + exact gelu
    float t0 = b1[j], t1 = b1[j + 128];
    #pragma unroll 8
    for (int d = 0; d < HH; d++) {
        float md = m_s[ka][d];
        t0 += md * g_W1T[d * 256 + j];
        t1 += md * g_W1T[d * 256 + j + 128];
    }
    t_s[ka][j] = gelu_exact(t0);
    t_s[ka][j + 128] = gelu_exact(t1);
    __syncthreads();

    // MLP project + residual
    float o = hnew + b2[j];
    #pragma unroll 8
    for (int p = 0; p < 2 * HH; p++) o += t_s[ka][p] * g_W2T[p * HH + j];

    int idx = (b * KK + ka) * HH + j;
    g_slots[idx] = o;
    out_slots[idx] = o;
}

// ------------------------- launch ---------------------------------------------
extern "C" void kernel_launch(void* const* d_in, const int* in_sizes, int n_in,
                              void* d_out, int out_size) {
    const float* X       = (const float*)d_in[0];
    const float* noise   = (const float*)d_in[1];
    const float* slot_mu = (const float*)d_in[2];
    const float* slot_ls = (const float*)d_in[3];
    const float* Wp  = (const float*)d_in[4];
    const float* bp  = (const float*)d_in[5];
    const float* gin = (const float*)d_in[6];
    const float* bin = (const float*)d_in[7];
    const float* Wq  = (const float*)d_in[8];
    const float* bq  = (const float*)d_in[9];
    const float* Wk  = (const float*)d_in[10];
    const float* bk  = (const float*)d_in[11];
    const float* Wv  = (const float*)d_in[12];
    const float* bv  = (const float*)d_in[13];
    const float* Wih = (const float*)d_in[14];
    const float* bih = (const float*)d_in[15];
    const float* Whh = (const float*)d_in[16];
    const float* bhh = (const float*)d_in[17];
    const float* gs  = (const float*)d_in[18];
    const float* bs  = (const float*)d_in[19];
    const float* W1  = (const float*)d_in[20];
    const float* b1  = (const float*)d_in[21];
    const float* W2  = (const float*)d_in[22];
    const float* b2  = (const float*)d_in[23];
    const float* gm  = (const float*)d_in[24];
    const float* bm  = (const float*)d_in[25];

    float* out_slots = (float*)d_out;                    // (B,K,H)
    float* out_attn  = (float*)d_out + BB * KK * HH;     // (B,K,N)

    prep_transpose<<<192, 256>>>(Wp, Wq, Wv, Wih, Whh, W1, W2);
    init_slots<<<BB * KK * HH / 512, 512>>>(noise, slot_mu, slot_ls);
    proj_ln_kernel<<<BN / TM, 256>>>(X, bp, gin, bin);

    for (int it = 0; it < 3; it++) {
        ln_q_kernel<<<BB, 384>>>(gs, bs, bq, Wk, bk);
        attn_stream_kernel<<<BB, 256>>>(out_attn);
        post_kernel<<<BB, 384>>>(bv, bih, bhh, gm, bm, b1, b2, out_slots);
    }
}

// round 6
// speedup vs baseline: 2.1430x; 2.1430x over previous
#include <cuda_runtime.h>
#include <math.h>

#define BB   128
#define NN   1024
#define DIN  192
#define HH   128
#define KK   3
#define BN   (BB*NN)
#define SCALE 0.08838834764831845f   // 1/sqrt(128)
#define LNEPS 1e-5f

// ------------------------- device scratch ------------------------------------
__device__ float g_inputs[(size_t)BN * HH];     // 64 MB
__device__ float g_WpT[DIN * HH];
__device__ float g_WqT[HH * HH];
__device__ float g_WvT[HH * HH];
__device__ float g_WihT[HH * 3 * HH];
__device__ float g_WhhT[HH * 3 * HH];
__device__ float g_W1T[HH * 2 * HH];
__device__ float g_W2T[2 * HH * HH];
__device__ float g_slots[BB * KK * HH];
__device__ float g_upd[BB * KK * HH];
__device__ float g_sumw[BB * KK];

typedef unsigned long long u64;

__device__ __forceinline__ u64 pack2(float lo, float hi) {
    u64 r; asm("mov.b64 %0, {%1,%2};" : "=l"(r) : "f"(lo), "f"(hi)); return r;
}
__device__ __forceinline__ void unpack2(u64 v, float& lo, float& hi) {
    asm("mov.b64 {%0,%1}, %2;" : "=f"(lo), "=f"(hi) : "l"(v));
}
__device__ __forceinline__ u64 fma2(u64 a, u64 b, u64 c) {
    u64 d; asm("fma.rn.f32x2 %0, %1, %2, %3;" : "=l"(d) : "l"(a), "l"(b), "l"(c)); return d;
}
__device__ __forceinline__ float wred(float v) {
    #pragma unroll
    for (int o = 16; o; o >>= 1) v += __shfl_xor_sync(0xFFFFFFFFu, v, o);
    return v;
}
__device__ __forceinline__ float sigmoidf_(float x) { return 1.0f / (1.0f + expf(-x)); }
__device__ __forceinline__ float gelu_exact(float x) {
    return 0.5f * x * (1.0f + erff(x * 0.7071067811865476f));
}

// ------------------------- weight transposes ---------------------------------
__global__ void prep_transpose(const float* __restrict__ Wp, const float* __restrict__ Wq,
                               const float* __restrict__ Wv, const float* __restrict__ Wih,
                               const float* __restrict__ Whh, const float* __restrict__ W1,
                               const float* __restrict__ W2) {
    int i = blockIdx.x * blockDim.x + threadIdx.x;
    int stride = gridDim.x * blockDim.x;
    for (int t = i; t < HH * DIN; t += stride) { int j = t / DIN, e = t % DIN; g_WpT[e * HH + j] = Wp[t]; }
    for (int t = i; t < HH * HH; t += stride) { int j = t / HH, e = t % HH; g_WqT[e * HH + j] = Wq[t]; }
    for (int t = i; t < HH * HH; t += stride) { int d = t / HH, e = t % HH; g_WvT[e * HH + d] = Wv[t]; }
    for (int t = i; t < 3 * HH * HH; t += stride) { int o = t / HH, d = t % HH; g_WihT[d * (3 * HH) + o] = Wih[t]; }
    for (int t = i; t < 3 * HH * HH; t += stride) { int o = t / HH, d = t % HH; g_WhhT[d * (3 * HH) + o] = Whh[t]; }
    for (int t = i; t < 2 * HH * HH; t += stride) { int p = t / HH, d = t % HH; g_W1T[d * (2 * HH) + p] = W1[t]; }
    for (int t = i; t < 2 * HH * HH; t += stride) { int j = t / (2 * HH), p = t % (2 * HH); g_W2T[p * HH + j] = W2[t]; }
}

__global__ void init_slots(const float* __restrict__ noise, const float* __restrict__ mu,
                           const float* __restrict__ logsig) {
    int i = blockIdx.x * blockDim.x + threadIdx.x;
    int r = i % (KK * HH);
    g_slots[i] = mu[r] + expf(logsig[r]) * noise[i];
}

// ------------------------- fused projection + LayerNorm (f32x2) --------------
// 64 rows x 128 cols per block, 256 threads. acc: 4 row-pairs x 4 cols (packed).
#define TM 64
#define KB 16
__global__ __launch_bounds__(256) void proj_ln_kernel(const float* __restrict__ X,
                                                      const float* __restrict__ bp,
                                                      const float* __restrict__ gin,
                                                      const float* __restrict__ bin) {
    __shared__ __align__(16) float xs_t[KB][66];   // [kk][row], padded
    __shared__ __align__(16) float ws[KB][HH];     // [kk][col]
    const int row0 = blockIdx.x * TM;
    const int tid = threadIdx.x;
    const int w = tid >> 5;      // 0..7 : row group (8 rows each)
    const int l = tid & 31;      // 0..31: col group (4 cols each)

    u64 acc[4][4];
    #pragma unroll
    for (int p = 0; p < 4; p++)
        #pragma unroll
        for (int c = 0; c < 4; c++) acc[p][c] = pack2(0.0f, 0.0f);

    const int ld_row = tid >> 2;   // 0..63
    const int ld_seg = tid & 3;    // 0..3

    for (int k0 = 0; k0 < DIN; k0 += KB) {
        // load X tile transposed: xs_t[kk][row]
        float4 xv = *(const float4*)(&X[(size_t)(row0 + ld_row) * DIN + k0 + ld_seg * 4]);
        xs_t[ld_seg * 4 + 0][ld_row] = xv.x;
        xs_t[ld_seg * 4 + 1][ld_row] = xv.y;
        xs_t[ld_seg * 4 + 2][ld_row] = xv.z;
        xs_t[ld_seg * 4 + 3][ld_row] = xv.w;
        // load W tile: ws[kk][j]
        #pragma unroll
        for (int i = 0; i < 2; i++) {
            int lin = i * 256 + tid;
            int kk = lin >> 5, jj = lin & 31;
            *(float4*)(&ws[kk][jj * 4]) = *(const float4*)(&g_WpT[(k0 + kk) * HH + jj * 4]);
        }
        __syncthreads();
        #pragma unroll
        for (int kk = 0; kk < KB; kk++) {
            float4 b4 = *(const float4*)(&ws[kk][l * 4]);
            u64 bx = pack2(b4.x, b4.x);
            u64 by = pack2(b4.y, b4.y);
            u64 bz = pack2(b4.z, b4.z);
            u64 bw = pack2(b4.w, b4.w);
            #pragma unroll
            for (int p = 0; p < 4; p++) {
                u64 a = *(const u64*)(&xs_t[kk][w * 8 + p * 2]);   // row pair, broadcast
                acc[p][0] = fma2(a, bx, acc[p][0]);
                acc[p][1] = fma2(a, by, acc[p][1]);
                acc[p][2] = fma2(a, bz, acc[p][2]);
                acc[p][3] = fma2(a, bw, acc[p][3]);
            }
        }
        __syncthreads();
    }

    const float4 bias = *(const float4*)(&bp[l * 4]);
    const float4 g4   = *(const float4*)(&gin[l * 4]);
    const float4 b4n  = *(const float4*)(&bin[l * 4]);

    #pragma unroll
    for (int p = 0; p < 4; p++) {
        float r0[4], r1[4];
        unpack2(acc[p][0], r0[0], r1[0]);
        unpack2(acc[p][1], r0[1], r1[1]);
        unpack2(acc[p][2], r0[2], r1[2]);
        unpack2(acc[p][3], r0[3], r1[3]);
        #pragma unroll
        for (int half = 0; half < 2; half++) {
            float* r = half ? r1 : r0;
            r[0] += bias.x; r[1] += bias.y; r[2] += bias.z; r[3] += bias.w;
            float s  = r[0] + r[1] + r[2] + r[3];
            float s2 = r[0]*r[0] + r[1]*r[1] + r[2]*r[2] + r[3]*r[3];
            s = wred(s); s2 = wred(s2);
            float mu = s * (1.0f / HH);
            float var = s2 * (1.0f / HH) - mu * mu;
            float rstd = rsqrtf(var + LNEPS);
            int row = row0 + w * 8 + p * 2 + half;
            float4 o;
            o.x = (r[0] - mu) * rstd * g4.x + b4n.x;
            o.y = (r[1] - mu) * rstd * g4.y + b4n.y;
            o.z = (r[2] - mu) * rstd * g4.z + b4n.z;
            o.w = (r[3] - mu) * rstd * g4.w + b4n.w;
            *(float4*)(&g_inputs[(size_t)row * HH + l * 4]) = o;
        }
    }
}

// ------------------------- fused LN/q/qk + attention stream ------------------
// grid = B, 512 threads (16 warps). Phase A: LN(slots), q, qk, c.
// Phase B: 32 half-warps, 16 lanes per token, 32 tokens each.
__global__ __launch_bounds__(512) void attn_fused_kernel(const float* __restrict__ gs,
                                                         const float* __restrict__ bs,
                                                         const float* __restrict__ bq,
                                                         const float* __restrict__ Wk,
                                                         const float* __restrict__ bk,
                                                         float* __restrict__ attn_out) {
    const int b = blockIdx.x;
    const int tid = threadIdx.x;
    const int wid = tid >> 5, lane = tid & 31;
    __shared__ float s_s[KK][HH];
    __shared__ float q_s[KK][HH];
    __shared__ float qk_s[KK][HH];
    __shared__ float c_s[KK];
    __shared__ float red1[12], red2[12];
    __shared__ float a_s[KK][NN];            // 12 KB
    __shared__ float wacc[16][KK][HH];       // 24 KB
    __shared__ float wsum_s[16][KK];

    // ---- Phase A1: LN(slots)
    if (tid < KK * HH) {
        const int ka = tid >> 7, j = tid & 127;
        float v = g_slots[(b * KK + ka) * HH + j];
        float a = wred(v), a2 = wred(v * v);
        if (lane == 0) { red1[wid] = a; red2[wid] = a2; }
        (void)j;
    }
    __syncthreads();
    if (tid < KK * HH) {
        const int ka = tid >> 7, j = tid & 127;
        float mu = (red1[ka*4] + red1[ka*4+1] + red1[ka*4+2] + red1[ka*4+3]) * (1.0f / HH);
        float var = (red2[ka*4] + red2[ka*4+1] + red2[ka*4+2] + red2[ka*4+3]) * (1.0f / HH) - mu * mu;
        float rstd = rsqrtf(var + LNEPS);
        float v = g_slots[(b * KK + ka) * HH + j];
        s_s[ka][j] = (v - mu) * rstd * gs[j] + bs[j];
    }
    __syncthreads();

    // ---- Phase A2: q = s@Wq^T + bq  (128 threads, 3 slots each)
    if (tid < HH) {
        const int j = tid;
        float a0 = 0.f, a1 = 0.f, a2 = 0.f;
        #pragma unroll 8
        for (int e = 0; e < HH; e++) {
            float wv = g_WqT[e * HH + j];
            a0 += s_s[0][e] * wv;
            a1 += s_s[1][e] * wv;
            a2 += s_s[2][e] * wv;
        }
        float bb = bq[j];
        q_s[0][j] = a0 + bb; q_s[1][j] = a1 + bb; q_s[2][j] = a2 + bb;
    }
    __syncthreads();

    // ---- Phase A3: qk = SCALE * q@Wk ; c = SCALE * q.bk
    if (tid < HH) {
        const int j = tid;
        float a0 = 0.f, a1 = 0.f, a2 = 0.f;
        #pragma unroll 8
        for (int d = 0; d < HH; d++) {
            float wv = Wk[d * HH + j];
            a0 += q_s[0][d] * wv;
            a1 += q_s[1][d] * wv;
            a2 += q_s[2][d] * wv;
        }
        qk_s[0][j] = a0 * SCALE; qk_s[1][j] = a1 * SCALE; qk_s[2][j] = a2 * SCALE;
    }
    if (tid < KK * HH) {
        const int ka = tid >> 7, j = tid & 127;
        float p = wred(q_s[ka][j] * bk[j]);
        if (lane == 0) red1[wid] = p;
    }
    __syncthreads();
    if (tid < KK)
        c_s[tid] = (red1[tid*4] + red1[tid*4+1] + red1[tid*4+2] + red1[tid*4+3]) * SCALE;
    __syncthreads();

    // ---- Phase B: stream tokens
    const int hw = tid >> 4;        // half-warp id 0..31
    const int lh = tid & 15;        // lane in half-warp
    float qv[KK][8];
    #pragma unroll
    for (int ka = 0; ka < KK; ka++)
        #pragma unroll
        for (int q = 0; q < 8; q++) qv[ka][q] = qk_s[ka][lh * 8 + q];
    const float c0 = c_s[0], c1 = c_s[1], c2 = c_s[2];

    float f[KK][8];
    #pragma unroll
    for (int ka = 0; ka < KK; ka++)
        #pragma unroll
        for (int q = 0; q < 8; q++) f[ka][q] = 0.f;
    float ws0 = 0.f, ws1 = 0.f, ws2 = 0.f;

    const float* inp = g_inputs + (size_t)b * NN * HH;
    #pragma unroll 2
    for (int t = 0; t < 32; t++) {
        int n = t * 32 + hw;
        float4 x0 = *(const float4*)(&inp[(size_t)n * HH + lh * 8]);
        float4 x1 = *(const float4*)(&inp[(size_t)n * HH + lh * 8 + 4]);
        float xr[8] = {x0.x, x0.y, x0.z, x0.w, x1.x, x1.y, x1.z, x1.w};
        float d0 = 0.f, d1 = 0.f, d2 = 0.f;
        #pragma unroll
        for (int q = 0; q < 8; q++) {
            d0 += xr[q] * qv[0][q];
            d1 += xr[q] * qv[1][q];
            d2 += xr[q] * qv[2][q];
        }
        #pragma unroll
        for (int o = 1; o < 16; o <<= 1) {
            d0 += __shfl_xor_sync(0xFFFFFFFFu, d0, o);
            d1 += __shfl_xor_sync(0xFFFFFFFFu, d1, o);
            d2 += __shfl_xor_sync(0xFFFFFFFFu, d2, o);
        }
        d0 += c0; d1 += c1; d2 += c2;
        float m = fmaxf(d0, fmaxf(d1, d2));
        float e0 = expf(d0 - m), e1 = expf(d1 - m), e2 = expf(d2 - m);
        float inv = 1.0f / (e0 + e1 + e2);
        float a0 = e0 * inv, a1 = e1 * inv, a2 = e2 * inv;
        if (lh == 0) { a_s[0][n] = a0; a_s[1][n] = a1; a_s[2][n] = a2; }
        #pragma unroll
        for (int q = 0; q < 8; q++) {
            f[0][q] += a0 * xr[q];
            f[1][q] += a1 * xr[q];
            f[2][q] += a2 * xr[q];
        }
        ws0 += a0; ws1 += a1; ws2 += a2;
    }
    // reduce the two half-warps of each warp
    #pragma unroll
    for (int ka = 0; ka < KK; ka++)
        #pragma unroll
        for (int q = 0; q < 8; q++)
            f[ka][q] += __shfl_xor_sync(0xFFFFFFFFu, f[ka][q], 16);
    ws0 += __shfl_xor_sync(0xFFFFFFFFu, ws0, 16);
    ws1 += __shfl_xor_sync(0xFFFFFFFFu, ws1, 16);
    ws2 += __shfl_xor_sync(0xFFFFFFFFu, ws2, 16);
    if (lane < 16) {
        #pragma unroll
        for (int ka = 0; ka < KK; ka++)
            #pragma unroll
            for (int q = 0; q < 8; q++)
                wacc[wid][ka][lane * 8 + q] = f[ka][q];
    }
    if (lane == 0) { wsum_s[wid][0] = ws0; wsum_s[wid][1] = ws1; wsum_s[wid][2] = ws2; }
    __syncthreads();

    if (tid < KK * HH) {
        const int ka = tid >> 7, e = tid & 127;
        float s = 0.f;
        #pragma unroll
        for (int ww = 0; ww < 16; ww++) s += wacc[ww][ka][e];
        g_upd[b * KK * HH + tid] = s;
    }
    if (tid < KK) {
        float s = 0.f;
        #pragma unroll
        for (int ww = 0; ww < 16; ww++) s += wsum_s[ww][tid];
        g_sumw[b * KK + tid] = s;
    }
    // coalesced attn write (a_s flat layout == output layout)
    const float* af = &a_s[0][0];
    float* ao = attn_out + (size_t)b * KK * NN;
    for (int i = tid; i < KK * NN; i += 512) ao[i] = af[i];
}

// ------------------------- updates -> GRU -> LN -> MLP -----------------------
// grid = B, 1024 threads; weights shared across the 3 slots (read once/block).
__global__ __launch_bounds__(1024) void post_kernel(const float* __restrict__ bv,
                                                    const float* __restrict__ bih,
                                                    const float* __restrict__ bhh,
                                                    const float* __restrict__ gm,
                                                    const float* __restrict__ bm,
                                                    const float* __restrict__ b1,
                                                    const float* __restrict__ b2,
                                                    float* __restrict__ out_slots) {
    const int b = blockIdx.x;
    const int tid = threadIdx.x;
    const int wid = tid >> 5, lane = tid & 31;
    __shared__ float upd_s[KK][HH];
    __shared__ float h_s[KK][HH];
    __shared__ float x_s[KK][HH];
    __shared__ float gi_s[KK][3 * HH];
    __shared__ float gh_s[KK][3 * HH];
    __shared__ float hn_s[KK][HH];
    __shared__ float m_s[KK][HH];
    __shared__ float t_s[KK][2 * HH];
    __shared__ float part_s[8][KK][2 * HH];   // split-K scratch (24 KB)
    __shared__ float sw_s[KK];
    __shared__ float red1[12], red2[12];

    if (tid < KK * HH) {
        upd_s[0][tid & 1023] = g_upd[b * KK * HH + tid];   // flat
        h_s[0][tid & 1023]   = g_slots[b * KK * HH + tid];
    }
    if (tid < KK) sw_s[tid] = g_sumw[b * KK + tid];
    __syncthreads();

    // ---- Phase 1: x = upd @ Wv^T + sumw*bv  (split-K8, 1024 threads)
    {
        const int j = tid & 127, part = tid >> 7;   // 8 parts x 16 elems
        float a0 = 0.f, a1 = 0.f, a2 = 0.f;
        const int e0 = part * 16;
        #pragma unroll
        for (int e = 0; e < 16; e++) {
            float wv = g_WvT[(e0 + e) * HH + j];
            a0 += upd_s[0][e0 + e] * wv;
            a1 += upd_s[1][e0 + e] * wv;
            a2 += upd_s[2][e0 + e] * wv;
        }
        part_s[part][0][j] = a0; part_s[part][1][j] = a1; part_s[part][2][j] = a2;
    }
    __syncthreads();
    if (tid < KK * HH) {
        const int ka = tid >> 7, j = tid & 127;
        float s = sw_s[ka] * bv[j];
        #pragma unroll
        for (int p = 0; p < 8; p++) s += part_s[p][ka][j];
        x_s[ka][j] = s;
    }
    __syncthreads();

    // ---- Phase 2: GRU gates (768 threads: 384 for ih, 384 for hh)
    if (tid < 768) {
        const int is_hh = tid >= 384;
        const int o = is_hh ? tid - 384 : tid;
        const float* W = is_hh ? g_WhhT : g_WihT;
        const float (*src)[HH] = is_hh ? h_s : x_s;
        float a0 = 0.f, a1 = 0.f, a2 = 0.f;
        #pragma unroll 4
        for (int d = 0; d < HH; d++) {
            float wv = W[d * 384 + o];
            a0 += src[0][d] * wv;
            a1 += src[1][d] * wv;
            a2 += src[2][d] * wv;
        }
        if (is_hh) {
            float bb = bhh[o];
            gh_s[0][o] = a0 + bb; gh_s[1][o] = a1 + bb; gh_s[2][o] = a2 + bb;
        } else {
            float bb = bih[o];
            gi_s[0][o] = a0 + bb; gi_s[1][o] = a1 + bb; gi_s[2][o] = a2 + bb;
        }
    }
    __syncthreads();

    // ---- Phase 3: gate combine + LN
    if (tid < KK * HH) {
        const int ka = tid >> 7, j = tid & 127;
        float r = sigmoidf_(gi_s[ka][j]       + gh_s[ka][j]);
        float z = sigmoidf_(gi_s[ka][128 + j] + gh_s[ka][128 + j]);
        float nn = tanhf(gi_s[ka][256 + j] + r * gh_s[ka][256 + j]);
        float hnew = (1.0f - z) * nn + z * h_s[ka][j];
        hn_s[ka][j] = hnew;
        float a = wred(hnew), a2 = wred(hnew * hnew);
        if (lane == 0) { red1[wid] = a; red2[wid] = a2; }
    }
    __syncthreads();
    if (tid < KK * HH) {
        const int ka = tid >> 7, j = tid & 127;
        float mu = (red1[ka*4] + red1[ka*4+1] + red1[ka*4+2] + red1[ka*4+3]) * (1.0f / HH);
        float var = (red2[ka*4] + red2[ka*4+1] + red2[ka*4+2] + red2[ka*4+3]) * (1.0f / HH) - mu * mu;
        float rstd = rsqrtf(var + LNEPS);
        m_s[ka][j] = (hn_s[ka][j] - mu) * rstd * gm[j] + bm[j];
    }
    __syncthreads();

    // ---- Phase 4: W1 + gelu (split-K4 over d: 1024 threads -> 256 cols x 4)
    {
        const int p = tid & 255, part = tid >> 8;   // 4 parts x 32 elems
        float a0 = 0.f, a1 = 0.f, a2 = 0.f;
        const int d0 = part * 32;
        #pragma unroll 8
        for (int d = 0; d < 32; d++) {
            float wv = g_W1T[(d0 + d) * (2 * HH) + p];
            a0 += m_s[0][d0 + d] * wv;
            a1 += m_s[1][d0 + d] * wv;
            a2 += m_s[2][d0 + d] * wv;
        }
        part_s[part][0][p] = a0; part_s[part][1][p] = a1; part_s[part][2][p] = a2;
    }
    __syncthreads();
    if (tid < KK * 2 * HH) {
        const int ka = tid >> 8, p = tid & 255;
        float s = b1[p];
        #pragma unroll
        for (int q = 0; q < 4; q++) s += part_s[q][ka][p];
        t_s[ka][p] = gelu_exact(s);
    }
    __syncthreads();

    // ---- Phase 5: W2 + residual (split-K8 over p: 128 cols x 8 parts)
    {
        const int j = tid & 127, part = tid >> 7;   // 8 parts x 32 elems
        float a0 = 0.f, a1 = 0.f, a2 = 0.f;
        const int p0 = part * 32;
        #pragma unroll 8
        for (int p = 0; p < 32; p++) {
            float wv = g_W2T[(p0 + p) * HH + j];
            a0 += t_s[0][p0 + p] * wv;
            a1 += t_s[1][p0 + p] * wv;
            a2 += t_s[2][p0 + p] * wv;
        }
        part_s[part][0][j] = a0; part_s[part][1][j] = a1; part_s[part][2][j] = a2;
    }
    __syncthreads();
    if (tid < KK * HH) {
        const int ka = tid >> 7, j = tid & 127;
        float o = hn_s[ka][j] + b2[j];
        #pragma unroll
        for (int p = 0; p < 8; p++) o += part_s[p][ka][j];
        int idx = b * KK * HH + tid;
        g_slots[idx] = o;
        out_slots[idx] = o;
    }
}

// ------------------------- launch --------------------------------------------
extern "C" void kernel_launch(void* const* d_in, const int* in_sizes, int n_in,
                              void* d_out, int out_size) {
    const float* X       = (const float*)d_in[0];
    const float* noise   = (const float*)d_in[1];
    const float* slot_mu = (const float*)d_in[2];
    const float* slot_ls = (const float*)d_in[3];
    const float* Wp  = (const float*)d_in[4];
    const float* bp  = (const float*)d_in[5];
    const float* gin = (const float*)d_in[6];
    const float* bin = (const float*)d_in[7];
    const float* Wq  = (const float*)d_in[8];
    const float* bq  = (const float*)d_in[9];
    const float* Wk  = (const float*)d_in[10];
    const float* bk  = (const float*)d_in[11];
    const float* Wv  = (const float*)d_in[12];
    const float* bv  = (const float*)d_in[13];
    const float* Wih = (const float*)d_in[14];
    const float* bih = (const float*)d_in[15];
    const float* Whh = (const float*)d_in[16];
    const float* bhh = (const float*)d_in[17];
    const float* gs  = (const float*)d_in[18];
    const float* bs  = (const float*)d_in[19];
    const float* W1  = (const float*)d_in[20];
    const float* b1  = (const float*)d_in[21];
    const float* W2  = (const float*)d_in[22];
    const float* b2  = (const float*)d_in[23];
    const float* gm  = (const float*)d_in[24];
    const float* bm  = (const float*)d_in[25];

    float* out_slots = (float*)d_out;
    float* out_attn  = (float*)d_out + BB * KK * HH;

    prep_transpose<<<192, 256>>>(Wp, Wq, Wv, Wih, Whh, W1, W2);
    init_slots<<<BB * KK * HH / 512, 512>>>(noise, slot_mu, slot_ls);
    proj_ln_kernel<<<BN / TM, 256>>>(X, bp, gin, bin);

    for (int it = 0; it < 3; it++) {
        attn_fused_kernel<<<BB, 512>>>(gs, bs, bq, Wk, bk, out_attn);
        post_kernel<<<BB, 1024>>>(bv, bih, bhh, gm, bm, b1, b2, out_slots);
    }
}